// round 8
// baseline (speedup 1.0000x reference)
#include <cuda_runtime.h>
#include <cuda_fp16.h>
#include <cstdint>

// ----------------------------------------------------------------------------
// fp16 mma.sync m16n8k16 + ldmatrix, cp.async.bulk (1D) + mbarrier pipeline.
// R8: stage-boundary full-barrier wait hoisted into kk=3 of the previous
// stage (before its MMAs issue), so each warp stalls with ~32 HMMAs queued
// and the tensor pipe never drains at stage boundaries.
//
//   h = relu(x @ W_init^T + b_init)        M=32768 N=2048 K=1024
//   o = relu(h @ W_ih^T  + b_ih + b_hh)    M=32768 N=2048 K=2048
//   y =       o @ W_final^T + b_final      M=32768 N=1024 K=2048
//
// Persistent CTAs, CTA tile 128x256, BK=64, 4-stage pipeline, 8 warps.
// ----------------------------------------------------------------------------

#define DINLINE __device__ __forceinline__

static constexpr int DIN  = 1024;
static constexpr int DH   = 2048;
static constexpr int DACT = 1024;
static constexpr long MTOK = 32768;

static constexpr int BM = 128;
static constexpr int BN = 256;
static constexpr int BK = 64;            // 128B rows
static constexpr int STAGES = 4;
static constexpr int NTHR = 256;

static constexpr int A_ST = BM * BK * 2;         // 16384 B
static constexpr int B_ST = BN * BK * 2;         // 32768 B
static constexpr int STG  = A_ST + B_ST;         // 49152 B
static constexpr int HDR  = 1024;
static constexpr int SMEM_TOTAL = HDR + STAGES * STG;   // 197632

DINLINE uint32_t smem_u32(const void* p) {
    uint32_t a;
    asm("{ .reg .u64 t; cvta.to.shared.u64 t, %1; cvt.u32.u64 %0, t; }"
        : "=r"(a) : "l"(p));
    return a;
}

#define MBARRIER_INIT(addr, cnt) \
    asm volatile("mbarrier.init.shared.b64 [%0], %1;" :: "r"(addr), "r"(cnt) : "memory")
#define MBARRIER_ARRIVE(addr) \
    asm volatile("mbarrier.arrive.shared.b64 _, [%0];" :: "r"(addr) : "memory")
#define MBARRIER_EXPECT_TX(addr, n) \
    asm volatile("mbarrier.arrive.expect_tx.shared.b64 _, [%0], %1;" :: "r"(addr), "r"(n) : "memory")

#define MBARRIER_WAIT_PARITY(mbar_smem_addr, phase_parity) do { \
    uint32_t _mbar = (uint32_t)(mbar_smem_addr); \
    uint32_t _parity = (uint32_t)(phase_parity); \
    uint32_t _done; \
    asm volatile( \
        "{\n\t" \
        ".reg .pred p;\n\t" \
        "mbarrier.try_wait.parity.shared.b64 p, [%1], %2;\n\t" \
        "selp.b32 %0, 1, 0, p;\n\t" \
        "}" \
        : "=r"(_done) : "r"(_mbar), "r"(_parity) : "memory"); \
    if (!_done) { \
        asm volatile( \
            "{\n\t" \
            ".reg .pred P1;\n\t" \
            "WAIT_LOOP_%=:\n\t" \
            "mbarrier.try_wait.parity.shared.b64 P1, [%0], %1, 0x989680;\n\t" \
            "@P1 bra.uni WAIT_DONE_%=;\n\t" \
            "bra.uni WAIT_LOOP_%=;\n\t" \
            "WAIT_DONE_%=:\n\t" \
            "}" \
            :: "r"(_mbar), "r"(_parity) : "memory"); \
    } \
} while(0)

#define BULK_G2S(dst, src, sz, mbar) \
    asm volatile("cp.async.bulk.shared::cta.global.mbarrier::complete_tx::bytes [%0], [%1], %2, [%3];" \
        :: "r"((uint32_t)(dst)), "l"(src), "r"((uint32_t)(sz)), "r"((uint32_t)(mbar)) : "memory")

DINLINE void ldsm_x4(uint32_t* r, uint32_t addr) {
    asm volatile("ldmatrix.sync.aligned.m8n8.x4.shared.b16 {%0,%1,%2,%3}, [%4];"
        : "=r"(r[0]), "=r"(r[1]), "=r"(r[2]), "=r"(r[3]) : "r"(addr));
}

DINLINE void mma_f16(float* c, const uint32_t* a, const uint32_t* b) {
    asm volatile(
        "mma.sync.aligned.m16n8k16.row.col.f32.f16.f16.f32 "
        "{%0,%1,%2,%3}, {%4,%5,%6,%7}, {%8,%9}, {%0,%1,%2,%3};"
        : "+f"(c[0]), "+f"(c[1]), "+f"(c[2]), "+f"(c[3])
        : "r"(a[0]), "r"(a[1]), "r"(a[2]), "r"(a[3]), "r"(b[0]), "r"(b[1]));
}

// ----------------------------------------------------------------------------
// Scratch (static device allocations -- allowed). All in swizzled panel layout.
// ----------------------------------------------------------------------------
__device__ __half g_x [MTOK * DIN];
__device__ __half g_h [MTOK * DH];
__device__ __half g_o [MTOK * DH];
__device__ __half g_w1[(long)DH * DIN];
__device__ __half g_w2[(long)DH * DH];
__device__ __half g_w3[(long)DACT * DH];

// ----------------------------------------------------------------------------
// Fused fp32 -> fp16 + tile/swizzle pre-pass (all four tensors, one launch).
// ----------------------------------------------------------------------------
struct CvtSeg {
    const float* in;
    __half* out;
    int ng;        // granule count
    int kshift;    // log2(K/8)
    int rplog;     // log2(RP)
};

__global__ void __launch_bounds__(512, 2)
cvt_all_kernel(CvtSeg s0, CvtSeg s1, CvtSeg s2, CvtSeg s3, int total)
{
    for (int gi0 = blockIdx.x * blockDim.x + threadIdx.x; gi0 < total;
         gi0 += gridDim.x * blockDim.x) {
        CvtSeg s; int gi = gi0;
        if (gi < s0.ng) s = s0;
        else {
            gi -= s0.ng;
            if (gi < s1.ng) s = s1;
            else {
                gi -= s1.ng;
                if (gi < s2.ng) s = s2;
                else { gi -= s2.ng; s = s3; }
            }
        }
        const int gperrow = 1 << s.kshift;
        const int c8 = gi & (gperrow - 1);
        const int r  = gi >> s.kshift;
        const float4* f4 = reinterpret_cast<const float4*>(s.in);
        float4 v0 = f4[2 * (size_t)gi], v1 = f4[2 * (size_t)gi + 1];
        __half2 h0 = __floats2half2_rn(v0.x, v0.y), h1 = __floats2half2_rn(v0.z, v0.w);
        __half2 h2 = __floats2half2_rn(v1.x, v1.y), h3 = __floats2half2_rn(v1.z, v1.w);
        uint4 o = make_uint4(*reinterpret_cast<uint32_t*>(&h0), *reinterpret_cast<uint32_t*>(&h1),
                             *reinterpret_cast<uint32_t*>(&h2), *reinterpret_cast<uint32_t*>(&h3));
        const int rp = 1 << s.rplog;
        const size_t panel = (size_t)(r >> s.rplog) * (gperrow >> 3) + (c8 >> 3);
        const size_t gip   = (size_t)(r & (rp - 1)) * 8 + ((c8 & 7) ^ (r & 7));
        reinterpret_cast<uint4*>(s.out)[panel * ((size_t)rp * 8) + gip] = o;
    }
}

// ----------------------------------------------------------------------------
// Persistent GEMM: C = act(A @ B^T + bias1 (+bias2)); A,B in swizzled panels.
// ----------------------------------------------------------------------------
template <bool HALF_OUT, bool RELU>
__global__ void __launch_bounds__(NTHR, 1)
gemm_f16_kernel(const __half* __restrict__ A, const __half* __restrict__ Bw,
                void* __restrict__ Cv,
                const float* __restrict__ bias1, const float* __restrict__ bias2,
                int N, int ktlog, int ntlog, int Ttiles)
{
    extern __shared__ char smem[];
    const uint32_t sbase = smem_u32(smem);
    const int tid = threadIdx.x;
    const int wid = tid >> 5;
    const int lid = tid & 31;
    const int g   = lid >> 2;
    const int tg  = lid & 3;
    const int bid = blockIdx.x;
    const int grid = gridDim.x;
    const int KT = 1 << ktlog;
    const int ntmask = (1 << ntlog) - 1;

    const int warpM = wid >> 2;
    const int warpN = wid & 3;

    // mbarriers: full[s] @ 8s, empty[s] @ 64+8s
    if (tid == 0) {
        #pragma unroll
        for (int s = 0; s < STAGES; ++s) {
            MBARRIER_INIT(sbase + 8 * s, 1);
            MBARRIER_INIT(sbase + 64 + 8 * s, 8);
        }
    }
    __syncthreads();

    const int nMy = (bid < Ttiles) ? ((Ttiles - bid - 1) / grid + 1) : 0;
    if (nMy == 0) return;
    const long totIt = (long)nMy << ktlog;

    // map global iteration q -> (A panel, B panel) source pointers
    auto panels = [&](long q, const __half*& pa, const __half*& pb) {
        const int tIdx = (int)(q >> ktlog);
        const int kt   = (int)(q & (KT - 1));
        const int tile = bid + tIdx * grid;
        const int mtq  = tile >> ntlog;
        const int ntq  = tile & ntmask;
        pa = A  + ((size_t)mtq * KT + kt) * (A_ST / 2);
        pb = Bw + ((size_t)ntq * KT + kt) * (B_ST / 2);
    };

    // prologue: fill first min(STAGES-1, totIt) stages
    if (tid == 0) {
        #pragma unroll
        for (int s = 0; s < STAGES - 1; ++s) {
            if (s < totIt) {
                const __half *pa, *pb;
                panels(s, pa, pb);
                const uint32_t st = sbase + HDR + s * STG;
                MBARRIER_EXPECT_TX(sbase + 8 * s, STG);
                BULK_G2S(st,        pa, A_ST, sbase + 8 * s);
                BULK_G2S(st + A_ST, pb, B_ST, sbase + 8 * s);
            }
        }
    }

    // ldmatrix per-lane bases (swizzled granule addressing)
    const int lm   = lid >> 3;
    const int aRow = warpM * 64 + ((lm & 1) << 3) + (lid & 7);
    const int asel = lm >> 1;
    const int aXor = aRow & 7;
    const int bRow = warpN * 64 + ((lm >> 1) << 3) + (lid & 7);
    const int bsel = lm & 1;
    const int bXor = bRow & 7;
    uint32_t aBase[4], bBase[4];
    #pragma unroll
    for (int i = 0; i < 4; ++i) aBase[i] = (uint32_t)(aRow + i * 16) * 128;
    #pragma unroll
    for (int jp = 0; jp < 4; ++jp) bBase[jp] = (uint32_t)(bRow + jp * 16) * 128;

    // fragment double-buffer persists across stage AND tile boundaries
    uint32_t fa[2][4][4], fb[2][4][4];

    // pipeline prologue: wait stage 0, load its kk=0 fragments into buf 0
    {
        MBARRIER_WAIT_PARITY(sbase + 0, 0);
        const uint32_t sA0 = sbase + HDR;
        const uint32_t sB0 = sA0 + A_ST;
        const uint32_t aoff = (uint32_t)(((0 + asel) ^ aXor) << 4);
        const uint32_t boff = (uint32_t)(((0 + bsel) ^ bXor) << 4);
        #pragma unroll
        for (int i = 0; i < 4; ++i)    ldsm_x4(fa[0][i],  sA0 + aBase[i]  + aoff);
        #pragma unroll
        for (int jp = 0; jp < 4; ++jp) ldsm_x4(fb[0][jp], sB0 + bBase[jp] + boff);
    }

    for (int tl = 0; tl < nMy; ++tl) {
        const int tile = bid + tl * grid;
        const int mt = tile >> ntlog;
        const int nt = tile & ntmask;
        const long m0 = (long)mt * BM;
        const int  n0 = nt * BN;
        const long gbase = (long)tl << ktlog;

        float acc[4][8][4];
        #pragma unroll
        for (int i = 0; i < 4; ++i)
            #pragma unroll
            for (int j = 0; j < 8; ++j)
                #pragma unroll
                for (int e = 0; e < 4; ++e) acc[i][j][e] = 0.0f;

        for (int kt = 0; kt < KT; ++kt) {
            const long gi = gbase + kt;
            const int s = (int)(gi & (STAGES - 1));
            const uint32_t sA = sbase + HDR + s * STG;
            const uint32_t sB = sA + A_ST;

            // kk = 0..2: load kk+1 fragments, then mma kk
            #pragma unroll
            for (int kk = 0; kk < 3; ++kk) {
                const int cur = kk & 1, nxt = cur ^ 1;
                const uint32_t aoff = (uint32_t)((((kk + 1) * 2 + asel) ^ aXor) << 4);
                const uint32_t boff = (uint32_t)((((kk + 1) * 2 + bsel) ^ bXor) << 4);
                #pragma unroll
                for (int i = 0; i < 4; ++i)    ldsm_x4(fa[nxt][i],  sA + aBase[i]  + aoff);
                #pragma unroll
                for (int jp = 0; jp < 4; ++jp) ldsm_x4(fb[nxt][jp], sB + bBase[jp] + boff);
                #pragma unroll
                for (int i = 0; i < 4; ++i)
                    #pragma unroll
                    for (int j = 0; j < 8; ++j)
                        mma_f16(acc[i][j], fa[cur][i], &fb[cur][j >> 1][(j & 1) * 2]);
            }

            // kk = 3: wait NEXT stage + load its kk=0 fragments BEFORE issuing
            // kk=3's 32 MMAs — the wait is covered by the queued MMA work.
            if (gi + 1 < totIt) {
                const int sn = (int)((gi + 1) & (STAGES - 1));
                MBARRIER_WAIT_PARITY(sbase + 8 * sn, (uint32_t)(((gi + 1) >> 2) & 1));
                const uint32_t sAn = sbase + HDR + sn * STG;
                const uint32_t sBn = sAn + A_ST;
                const uint32_t aoff = (uint32_t)(((0 + asel) ^ aXor) << 4);
                const uint32_t boff = (uint32_t)(((0 + bsel) ^ bXor) << 4);
                #pragma unroll
                for (int i = 0; i < 4; ++i)    ldsm_x4(fa[0][i],  sAn + aBase[i]  + aoff);
                #pragma unroll
                for (int jp = 0; jp < 4; ++jp) ldsm_x4(fb[0][jp], sBn + bBase[jp] + boff);
            }
            #pragma unroll
            for (int i = 0; i < 4; ++i)
                #pragma unroll
                for (int j = 0; j < 8; ++j)
                    mma_f16(acc[i][j], fa[1][i], &fb[1][j >> 1][(j & 1) * 2]);

            __syncwarp();
            if (lid == 0) MBARRIER_ARRIVE(sbase + 64 + 8 * s);

            // producer: refill stage (gi + STAGES-1) — may belong to next tile
            const long pf = gi + STAGES - 1;
            if (tid == 0 && pf < totIt) {
                const int s2 = (int)(pf & (STAGES - 1));
                if (pf >= STAGES)
                    MBARRIER_WAIT_PARITY(sbase + 64 + 8 * s2, (uint32_t)(((pf >> 2) - 1) & 1));
                const __half *pa, *pb;
                panels(pf, pa, pb);
                const uint32_t st = sbase + HDR + s2 * STG;
                MBARRIER_EXPECT_TX(sbase + 8 * s2, STG);
                BULK_G2S(st,        pa, A_ST, sbase + 8 * s2);
                BULK_G2S(st + A_ST, pb, B_ST, sbase + 8 * s2);
            }
        }

        // ---- epilogue (next tile's kk0 fragments already in regs) ----------
        const bool has2 = (bias2 != nullptr);
        const int jb0 = n0 + warpN * 64;

        #pragma unroll
        for (int j = 0; j < 8; ++j) {
            const int col = jb0 + j * 8 + 2 * tg;
            float bb0 = bias1[col], bb1 = bias1[col + 1];
            if (has2) { bb0 += bias2[col]; bb1 += bias2[col + 1]; }
            #pragma unroll
            for (int i = 0; i < 4; ++i) {
                const long r0 = m0 + warpM * 64 + i * 16 + g;
                #pragma unroll
                for (int h = 0; h < 2; ++h) {
                    const long r = r0 + 8 * h;
                    float v0 = acc[i][j][2 * h + 0] + bb0;
                    float v1 = acc[i][j][2 * h + 1] + bb1;
                    if (RELU) { v0 = fmaxf(v0, 0.0f); v1 = fmaxf(v1, 0.0f); }
                    if (HALF_OUT) {
                        // swizzled 128-row panel layout (next GEMM's A operand)
                        __half2 hv = __floats2half2_rn(v0, v1);
                        const size_t panel = ((size_t)(r >> 7) * (N >> 6) + (col >> 6)) << 13;
                        const size_t off = panel + (size_t)((int)(r & 127)) * 64
                                         + (size_t)(((((col >> 3) & 7) ^ ((int)r & 7)) << 3) + (col & 7));
                        *reinterpret_cast<uint32_t*>((__half*)Cv + off) =
                            *reinterpret_cast<uint32_t*>(&hv);
                    } else {
                        *reinterpret_cast<float2*>((float*)Cv + (size_t)r * N + col) =
                            make_float2(v0, v1);
                    }
                }
            }
        }
    }
}

// ----------------------------------------------------------------------------
// Host launcher
// ----------------------------------------------------------------------------
extern "C" void kernel_launch(void* const* d_in, const int* in_sizes, int n_in,
                              void* d_out, int out_size)
{
    const float* x    = (const float*)d_in[0];
    const float* W1   = (const float*)d_in[1];
    const float* b1   = (const float*)d_in[2];
    const float* W2   = (const float*)d_in[3];
    const float* bih  = (const float*)d_in[4];
    const float* bhh  = (const float*)d_in[5];
    const float* W3   = (const float*)d_in[6];
    const float* b3   = (const float*)d_in[7];
    float* out = (float*)d_out;

    __half *gx, *gh, *go, *gw1, *gw2, *gw3;
    cudaGetSymbolAddress((void**)&gx,  g_x);
    cudaGetSymbolAddress((void**)&gh,  g_h);
    cudaGetSymbolAddress((void**)&go,  g_o);
    cudaGetSymbolAddress((void**)&gw1, g_w1);
    cudaGetSymbolAddress((void**)&gw2, g_w2);
    cudaGetSymbolAddress((void**)&gw3, g_w3);

    cudaFuncSetAttribute(gemm_f16_kernel<true, true>,
                         cudaFuncAttributeMaxDynamicSharedMemorySize, SMEM_TOTAL);
    cudaFuncSetAttribute(gemm_f16_kernel<false, false>,
                         cudaFuncAttributeMaxDynamicSharedMemorySize, SMEM_TOTAL);

    int nsm = 148;
    cudaDeviceGetAttribute(&nsm, cudaDevAttrMultiProcessorCount, 0);

    // fused pre-pass: fp32 -> fp16 into swizzled panels (single launch)
    {
        CvtSeg s0 = { x,  gx,  (int)(MTOK * (long)DIN / 8), 7, 7 };   // RP=128
        CvtSeg s1 = { W1, gw1, (int)((long)DH * DIN / 8),   7, 8 };   // RP=256
        CvtSeg s2 = { W2, gw2, (int)((long)DH * DH / 8),    8, 8 };
        CvtSeg s3 = { W3, gw3, (int)((long)DACT * DH / 8),  8, 8 };
        const int total = s0.ng + s1.ng + s2.ng + s3.ng;
        cvt_all_kernel<<<2048, 512>>>(s0, s1, s2, s3, total);
    }

    const int Mtiles = (int)(MTOK / BM);   // 256

    // GEMM1: h = relu(x @ W1^T + b1) -> fp16 panels   (KT=16, ktlog=4, ntlog=3)
    gemm_f16_kernel<true, true><<<nsm, NTHR, SMEM_TOTAL>>>(
        gx, gw1, gh, b1, nullptr, DH, 4, 3, Mtiles * (DH / BN));

    // GEMM2: o = relu(h @ W2^T + bih + bhh) -> fp16 panels (KT=32, ktlog=5, ntlog=3)
    gemm_f16_kernel<true, true><<<nsm, NTHR, SMEM_TOTAL>>>(
        gh, gw2, go, bih, bhh, DH, 5, 3, Mtiles * (DH / BN));

    // GEMM3: y = o @ W3^T + b3 -> fp32 row-major      (KT=32, ktlog=5, ntlog=2)
    gemm_f16_kernel<false, false><<<nsm, NTHR, SMEM_TOTAL>>>(
        go, gw3, out, b3, nullptr, DACT, 5, 2, Mtiles * (DACT / BN));

    (void)in_sizes; (void)n_in; (void)out_size;
}